// round 6
// baseline (speedup 1.0000x reference)
#include <cuda_runtime.h>
#include <cuda_fp16.h>
#include <cstdint>

// Problem constants (fixed by the reference: N=50000, K=32, FN=128, FE=64)
#define NMAX   50048          // 50000 padded to multiple of 128
#define FN     128
#define FE     64

typedef unsigned long long ull;

// Scratch (device globals: allocation-free per harness rules)
__device__ float  g_Wqk[128 * 64];        // wq @ wk^T
__device__ float  g_q2[NMAX * 64];        // nodes @ (wq @ wk^T)   [N, FE] fp32
__device__ __half g_nv[NMAX * 128];       // nodes @ wv            [N, FN] fp16

// ---------------------------------------------------------------------------
// packed fp32x2 helpers
// ---------------------------------------------------------------------------
__device__ __forceinline__ ull dup2(float x) {
    ull d;
    asm("mov.b64 %0, {%1, %1};" : "=l"(d) : "f"(x));
    return d;
}
#define FMA2(d, a, b) \
    asm("fma.rn.f32x2 %0, %1, %2, %0;" : "+l"(d) : "l"(a), "l"(b))
#define UNPACK2(lo, hi, v) \
    asm("mov.b64 {%0, %1}, %2;" : "=f"(lo), "=f"(hi) : "l"(v))

// ---------------------------------------------------------------------------
// K0: Wqk[i][e] = sum_f wq[i,f] * wk[e,f]    (128x64 outputs)
// grid = 16 blocks x 512 threads; block b computes rows 8b..8b+7.
// wk cached in padded smem (conflict-free), all global loads coalesced.
// ---------------------------------------------------------------------------
__global__ __launch_bounds__(512) void k0_wqk(const float* __restrict__ wq,
                                              const float* __restrict__ wk) {
    __shared__ float s_wk[64][65];   // padded: bank-conflict-free row reads
    __shared__ float s_wq[8][64];
    int t = threadIdx.x;

    // load wk (4096 floats) coalesced as float4, scatter into padded smem
    const float4* wk4 = (const float4*)wk;
#pragma unroll
    for (int i = 0; i < 2; ++i) {
        int idx = t + i * 512;           // 0..1023 float4s
        float4 v = wk4[idx];
        int r = (idx * 4) >> 6;
        int c = (idx * 4) & 63;
        s_wk[r][c + 0] = v.x;
        s_wk[r][c + 1] = v.y;
        s_wk[r][c + 2] = v.z;
        s_wk[r][c + 3] = v.w;
    }
    // load 8 wq rows (512 floats = 128 float4)
    if (t < 128) {
        float4 v = ((const float4*)(wq + blockIdx.x * 8 * 64))[t];
        int r = (t * 4) >> 6;
        int c = (t * 4) & 63;
        s_wq[r][c + 0] = v.x;
        s_wq[r][c + 1] = v.y;
        s_wq[r][c + 2] = v.z;
        s_wq[r][c + 3] = v.w;
    }
    __syncthreads();

    int i = t >> 6;      // 0..7 (local row)
    int e = t & 63;      // output col
    float s = 0.f;
#pragma unroll
    for (int f = 0; f < 64; ++f) s = fmaf(s_wq[i][f], s_wk[e][f], s);
    g_Wqk[(blockIdx.x * 8 + i) * 64 + e] = s;
}

// ---------------------------------------------------------------------------
// K1: SGEMM  [N,128] @ [Wqk | wv][128,192] -> g_q2 (fp32), g_nv (fp16)
// 256 threads, block tile 128r x 192c, thread tile 8r x 12c (f32x2 col-pairs).
// A stored in smem PRE-DUPLICATED as u64 {a,a} (no mov.b64 in inner loop).
// Double-buffered k-chunks (32 k each), register prefetch, 1 barrier/chunk.
// Dynamic smem: 2*32KB (As2) + 2*24KB (Bs) = 112 KB.
// ---------------------------------------------------------------------------
#define K1_SMEM (2 * 32 * 128 * 8 + 2 * 32 * 192 * 4)

__global__ __launch_bounds__(256) void k1_gemm(const float* __restrict__ nodes,
                                               const float* __restrict__ wv,
                                               int N) {
    extern __shared__ __align__(16) char sm[];
    ull   (*As2)[128] = (ull(*)[128])sm;                       // [2*32][128]
    float (*Bs)[192]  = (float(*)[192])(sm + 2 * 32 * 128 * 8); // [2*32][192]

    int t  = threadIdx.x;
    int tx = t & 15;          // col group: cols tx*12 .. +11
    int ty = t >> 4;          // row group: rows ty*8  .. +7
    int m0 = blockIdx.x * 128;

    int arow = t >> 3;        // A loader: rows arow + i*32
    int akq  = t & 7;         // float4 index within 32-k chunk

    ull acc[8][6];
#pragma unroll
    for (int r = 0; r < 8; ++r)
#pragma unroll
        for (int c = 0; c < 6; ++c) acc[r][c] = 0ull;

    const float4* nodes4 = (const float4*)nodes;
    const float4* wqk4   = (const float4*)g_Wqk;
    const float4* wv4    = (const float4*)wv;

    float4 pa[4], pb[6];

    // ---- chunk loaders (global -> regs, regs -> smem) ----
#define LOAD_CHUNK(ko)                                                        \
    do {                                                                      \
        _Pragma("unroll")                                                     \
        for (int i = 0; i < 4; ++i) {                                         \
            int row = arow + i * 32;                                          \
            int gr  = m0 + row;                                               \
            if (gr > N - 1) gr = N - 1;                                       \
            pa[i] = nodes4[(size_t)gr * 32 + (ko) * 8 + akq];                 \
        }                                                                     \
        _Pragma("unroll")                                                     \
        for (int i = 0; i < 6; ++i) {                                         \
            int p  = t + i * 256;                                             \
            int br = p / 48;                                                  \
            int bc = p % 48;                                                  \
            int gk = (ko) * 32 + br;                                          \
            pb[i] = (bc < 16) ? wqk4[gk * 16 + bc] : wv4[gk * 32 + (bc - 16)];\
        }                                                                     \
    } while (0)

#define STORE_CHUNK(buf)                                                      \
    do {                                                                      \
        _Pragma("unroll")                                                     \
        for (int i = 0; i < 4; ++i) {                                         \
            int row = arow + i * 32;                                          \
            As2[(buf) * 32 + akq * 4 + 0][row] = dup2(pa[i].x);               \
            As2[(buf) * 32 + akq * 4 + 1][row] = dup2(pa[i].y);               \
            As2[(buf) * 32 + akq * 4 + 2][row] = dup2(pa[i].z);               \
            As2[(buf) * 32 + akq * 4 + 3][row] = dup2(pa[i].w);               \
        }                                                                     \
        _Pragma("unroll")                                                     \
        for (int i = 0; i < 6; ++i) {                                         \
            int p  = t + i * 256;                                             \
            int br = p / 48;                                                  \
            int bc = p % 48;                                                  \
            ((float4*)&Bs[(buf) * 32 + br][0])[bc] = pb[i];                   \
        }                                                                     \
    } while (0)

    LOAD_CHUNK(0);
    STORE_CHUNK(0);
    __syncthreads();

#pragma unroll
    for (int ko = 0; ko < 4; ++ko) {
        if (ko < 3) LOAD_CHUNK(ko + 1);     // global loads in flight over compute
        int b = (ko & 1) * 32;

#pragma unroll 4
        for (int kk = 0; kk < 32; ++kk) {
            const ull* ar = &As2[b + kk][ty * 8];
            ulonglong2 A01 = *(const ulonglong2*)&ar[0];
            ulonglong2 A23 = *(const ulonglong2*)&ar[2];
            ulonglong2 A45 = *(const ulonglong2*)&ar[4];
            ulonglong2 A67 = *(const ulonglong2*)&ar[6];
            ull a2[8] = {A01.x, A01.y, A23.x, A23.y, A45.x, A45.y, A67.x, A67.y};

            const float* brow = &Bs[b + kk][tx * 12];
            ulonglong2 b01 = *(const ulonglong2*)&brow[0];
            ulonglong2 b23 = *(const ulonglong2*)&brow[4];
            ulonglong2 b45 = *(const ulonglong2*)&brow[8];
            ull bb[6] = {b01.x, b01.y, b23.x, b23.y, b45.x, b45.y};

#pragma unroll
            for (int r = 0; r < 8; ++r)
#pragma unroll
                for (int c = 0; c < 6; ++c) FMA2(acc[r][c], a2[r], bb[c]);
        }

        if (ko < 3) STORE_CHUNK((ko + 1) & 1);
        __syncthreads();
    }

    // ---- epilogue: cols <64 -> g_q2 fp32 ; cols >=64 -> g_nv fp16 ----
#pragma unroll
    for (int r = 0; r < 8; ++r) {
        int row = m0 + ty * 8 + r;
#pragma unroll
        for (int c = 0; c < 6; ++c) {
            float lo, hi;
            UNPACK2(lo, hi, acc[r][c]);
            int col = tx * 12 + c * 2;
            if (col < 64) {
                *(float2*)&g_q2[row * 64 + col] = make_float2(lo, hi);
            } else {
                __half2 h = __float22half2_rn(make_float2(lo, hi));
                *(__half2*)&g_nv[row * 128 + (col - 64)] = h;
            }
        }
    }
#undef LOAD_CHUNK
#undef STORE_CHUNK
}

// ---------------------------------------------------------------------------
// K2: logits (edges . q2) * inv_degree, softmax over K=32,
//     out[n] = sum_k b_k * g_nv[nlist[n,k]]   (fp16 gather, fp32 accum)
// grid = N blocks, 128 threads. Edge loads issued before any barrier;
// softmax done redundantly per-warp in registers (3 barriers total).
// ---------------------------------------------------------------------------
__global__ __launch_bounds__(128) void k2_main(const float* __restrict__ edges,
                                               const int*   __restrict__ nlist,
                                               const float* __restrict__ inv_degree,
                                               float*       __restrict__ out) {
    int n = blockIdx.x;
    int t = threadIdx.x;
    int w = t >> 5;           // warp 0..3
    int l = t & 31;           // lane

    __shared__ __align__(16) float s_q2[64];
    __shared__ float s_l[32];
    __shared__ int   s_idx[32];
    __shared__ __align__(16) float s_red[4][128];

    // ---- edge loads FIRST (DRAM latency starts before the barrier) ----
    int k = t >> 2;
    int q = t & 3;
    const float4* e4 = (const float4*)edges + (size_t)n * 512 + k * 16 + q * 4;
    float4 e0 = __ldcs(&e4[0]);
    float4 e1 = __ldcs(&e4[1]);
    float4 e2 = __ldcs(&e4[2]);
    float4 e3 = __ldcs(&e4[3]);

    if (t < 64) s_q2[t] = g_q2[n * 64 + t];
    if (t >= 64 && t < 96) s_idx[t - 64] = nlist[n * 32 + (t - 64)];
    float inv = __ldg(&inv_degree[n]);
    __syncthreads();

    // ---- logits: 4 threads per k, 16 features each ----
    {
        const float4* w4 = (const float4*)&s_q2[q * 16];
        float4 w0 = w4[0], w1 = w4[1], w2 = w4[2], w3 = w4[3];
        float p = 0.f;
        p = fmaf(e0.x, w0.x, p); p = fmaf(e0.y, w0.y, p);
        p = fmaf(e0.z, w0.z, p); p = fmaf(e0.w, w0.w, p);
        p = fmaf(e1.x, w1.x, p); p = fmaf(e1.y, w1.y, p);
        p = fmaf(e1.z, w1.z, p); p = fmaf(e1.w, w1.w, p);
        p = fmaf(e2.x, w2.x, p); p = fmaf(e2.y, w2.y, p);
        p = fmaf(e2.z, w2.z, p); p = fmaf(e2.w, w2.w, p);
        p = fmaf(e3.x, w3.x, p); p = fmaf(e3.y, w3.y, p);
        p = fmaf(e3.z, w3.z, p); p = fmaf(e3.w, w3.w, p);
        p += __shfl_xor_sync(0xffffffffu, p, 1);
        p += __shfl_xor_sync(0xffffffffu, p, 2);
        if (q == 0) s_l[k] = p * inv;
    }
    __syncthreads();

    // ---- per-warp softmax over K=32 (redundant in each warp, no extra barrier) ----
    float lg = s_l[l];
    float m = lg;
#pragma unroll
    for (int o = 16; o; o >>= 1) m = fmaxf(m, __shfl_xor_sync(0xffffffffu, m, o));
    float ex = __expf(lg - m);
    float sum = ex;
#pragma unroll
    for (int o = 16; o; o >>= 1) sum += __shfl_xor_sync(0xffffffffu, sum, o);
    float bl = ex / sum;      // lane l holds b[l]

    // ---- weighted fp16 gather: warp w handles k in [w*8, w*8+8),
    //      lane l loads 8B = 4 features (cols 4l..4l+3) ----
    float4 acc = make_float4(0.f, 0.f, 0.f, 0.f);
#pragma unroll
    for (int kk = 0; kk < 8; ++kk) {
        int   ki  = w * 8 + kk;
        float bw  = __shfl_sync(0xffffffffu, bl, ki);
        int   row = s_idx[ki];
        uint2 v = *(const uint2*)&g_nv[(size_t)row * 128 + l * 4];
        float2 f0 = __half22float2(*(__half2*)&v.x);
        float2 f1 = __half22float2(*(__half2*)&v.y);
        acc.x = fmaf(bw, f0.x, acc.x);
        acc.y = fmaf(bw, f0.y, acc.y);
        acc.z = fmaf(bw, f1.x, acc.z);
        acc.w = fmaf(bw, f1.y, acc.w);
    }
    *(float4*)&s_red[w][l * 4] = acc;
    __syncthreads();

    // ---- cross-warp reduce + streaming store ----
    float r0 = s_red[0][t] + s_red[1][t];
    float r1 = s_red[2][t] + s_red[3][t];
    __stcs(&out[(size_t)n * 128 + t], r0 + r1);
}

// ---------------------------------------------------------------------------
// Inputs (metadata order): nodes f32[N,128], nlist i32[N,32], edges f32[N,32,64],
//                          inv_degree f32[N], wq f32[128,64], wk f32[64,64],
//                          wv f32[128,128]
// Output: f32[N,128]
// ---------------------------------------------------------------------------
extern "C" void kernel_launch(void* const* d_in, const int* in_sizes, int n_in,
                              void* d_out, int out_size) {
    const float* nodes      = (const float*)d_in[0];
    const int*   nlist      = (const int*)  d_in[1];
    const float* edges      = (const float*)d_in[2];
    const float* inv_degree = (const float*)d_in[3];
    const float* wq         = (const float*)d_in[4];
    const float* wk         = (const float*)d_in[5];
    const float* wv         = (const float*)d_in[6];
    float*       out        = (float*)d_out;

    int N = in_sizes[0] / FN;   // 50000

    // idempotent, host-side, not enqueued: safe under graph capture
    cudaFuncSetAttribute(k1_gemm, cudaFuncAttributeMaxDynamicSharedMemorySize,
                         K1_SMEM);

    k0_wqk<<<16, 512>>>(wq, wk);
    k1_gemm<<<(N + 127) / 128, 256, K1_SMEM>>>(nodes, wv, N);
    k2_main<<<N, 128>>>(edges, nlist, inv_degree, out);
}